// round 15
// baseline (speedup 1.0000x reference)
#include <cuda_runtime.h>
#include <cuda_bf16.h>
#include <cstdint>

#define NN 65536
#define DD 512
#define HH 256
#define KC 16
#define LV 3
#define CC 64
#define CK 1024
#define NH 768
#define GAP_TH 5e-3f
#define RB 16          // recheck batch rows
#define XR_PITCH 516   // padded row pitch for xr (breaks bank conflicts)

__device__ float g_claccum[CC*DD];
__device__ int   g_seg[NN];
__device__ float g_means[CK*DD];
__device__ float g_cnt[CK];
__device__ int   g_cntI[CK];
__device__ int   g_segbase[CK];
__device__ int   g_hist[128*CK];   // [block][seg]
__device__ int   g_order[NN];
__device__ float g_h[CK*DD];
__device__ float g_ref[CK*DD];
__device__ float g_lp[LV*CC*DD];
__device__ float g_cw1[CC*HH];
__device__ int   g_amb[NN];
__device__ int   g_ambN;
__device__ __nv_bfloat16 g_hidb[(size_t)NN*NH];
__device__ __nv_bfloat16 g_xhi[(size_t)NN*DD];
__device__ __nv_bfloat16 g_w1hi[NH*DD];

__device__ __forceinline__ uint32_t smem_u32(const void* p) {
    uint32_t a;
    asm("{ .reg .u64 t; cvta.to.shared.u64 t, %1; cvt.u32.u64 %0, t; }" : "=r"(a) : "l"(p));
    return a;
}
__device__ __forceinline__ void cpa16(uint32_t dst, const void* src) {
    asm volatile("cp.async.cg.shared.global [%0], [%1], 16;" :: "r"(dst), "l"(src));
}
__device__ __forceinline__ void ldsm4(unsigned &r0, unsigned &r1, unsigned &r2, unsigned &r3, uint32_t a) {
    asm volatile("ldmatrix.sync.aligned.m8n8.x4.shared.b16 {%0,%1,%2,%3}, [%4];"
                 : "=r"(r0), "=r"(r1), "=r"(r2), "=r"(r3) : "r"(a));
}
#define MMA_BF16(d, a, b) \
    asm volatile("mma.sync.aligned.m16n8k16.row.col.f32.bf16.bf16.f32 " \
        "{%0,%1,%2,%3},{%4,%5,%6,%7},{%8,%9},{%0,%1,%2,%3};" \
        : "+f"((d)[0]), "+f"((d)[1]), "+f"((d)[2]), "+f"((d)[3]) \
        : "r"((a)[0]), "r"((a)[1]), "r"((a)[2]), "r"((a)[3]), "r"((b)[0]), "r"((b)[1]))

// init: zero claccum + hist, seed level-0 cw1 = b1, reset amb counter
__global__ void init_kernel(const float* __restrict__ b1_0) {
    int i = blockIdx.x * blockDim.x + threadIdx.x;
    if (i < CC*DD) g_claccum[i] = 0.f;
    if (i < CC*HH) g_cw1[i] = b1_0[i & (HH-1)];
#pragma unroll
    for (int u = 0; u < 4; u++) g_hist[i*4 + u] = 0;
    if (i == 0) g_ambN = 0;
}

__global__ void conv_x_kernel(const float* __restrict__ X) {
    for (size_t i = blockIdx.x * blockDim.x + threadIdx.x; i < (size_t)NN*DD/4;
         i += (size_t)gridDim.x * blockDim.x) {
        float4 v = ((const float4*)X)[i];
        __nv_bfloat162* dh = (__nv_bfloat162*)(g_xhi + 4*i);
        dh[0] = __nv_bfloat162(__float2bfloat16(v.x), __float2bfloat16(v.y));
        dh[1] = __nv_bfloat162(__float2bfloat16(v.z), __float2bfloat16(v.w));
    }
}
__global__ void conv_w1_kernel(const float* __restrict__ w1) {
    int i = blockIdx.x * blockDim.x + threadIdx.x;
    if (i >= LV*DD*HH) return;
    int l = i / (DD*HH);
    int r = i % (DD*HH);
    int k = r / HH, h = r % HH;
    size_t dst = (size_t)(l*HH + h) * DD + k;
    g_w1hi[dst] = __float2bfloat16(w1[i]);
}

// HID[N,768] = X @ W1cat, plain bf16 (argmax protected by fp32 recheck band),
// CTA 128x64, BK=32, 3-stage cp.async pipeline; HID stored bf16.
#define STG_B  15360
#define BHI_O  10240

__global__ __launch_bounds__(256) void gemm_hid_kernel() {
    extern __shared__ __nv_bfloat16 smbuf[];
    uint32_t smb = smem_u32(smbuf);
    int tid = threadIdx.x, lane = tid & 31, wid = tid >> 5;
    int warp_m = wid >> 1, warp_n = wid & 1;
    int blockN = blockIdx.x * 64;
    int blockM = blockIdx.y * 128;

    int a_r0 = tid >> 2, a_c = tid & 3;
    int a_r1 = a_r0 + 64;
    int b_r = tid >> 2;

    int a_row_off = lane & 15, a_k8 = (lane >> 4) * 8;
    int bm = lane >> 3;
    int b_n_off = ((bm >> 1) << 3) + (lane & 7);
    int b_k8 = (bm & 1) << 3;

    uint32_t addrA[2], addrB[2];
#pragma unroll
    for (int i = 0; i < 2; i++)
        addrA[i] = smb + (uint32_t)((warp_m*32 + i*16 + a_row_off)*40 + a_k8)*2;
#pragma unroll
    for (int j2 = 0; j2 < 2; j2++)
        addrB[j2] = smb + BHI_O + (uint32_t)((warp_n*32 + j2*16 + b_n_off)*40 + b_k8)*2;

    float acc[2][4][4];
#pragma unroll
    for (int i = 0; i < 2; i++)
#pragma unroll
        for (int j = 0; j < 4; j++)
#pragma unroll
            for (int q = 0; q < 4; q++) acc[i][j][q] = 0.f;

    auto issue = [&](int kt, int stage) {
        int kb = kt * 32;
        uint32_t sb = smb + stage * STG_B;
        size_t g0 = (size_t)(blockM + a_r0)*DD + kb + a_c*8;
        cpa16(sb + (uint32_t)(a_r0*40 + a_c*8)*2, g_xhi + g0);
        size_t g1 = (size_t)(blockM + a_r1)*DD + kb + a_c*8;
        cpa16(sb + (uint32_t)(a_r1*40 + a_c*8)*2, g_xhi + g1);
        size_t gb = (size_t)(blockN + b_r)*DD + kb + a_c*8;
        cpa16(sb + BHI_O + (uint32_t)(b_r*40 + a_c*8)*2, g_w1hi + gb);
        asm volatile("cp.async.commit_group;");
    };

    issue(0, 0);
    issue(1, 1);

    for (int kt = 0; kt < 16; kt++) {
        if (kt < 15) asm volatile("cp.async.wait_group 1;");
        else         asm volatile("cp.async.wait_group 0;");
        __syncthreads();
        int st = kt % 3;
        if (kt + 2 < 16) issue(kt + 2, (kt + 2) % 3);
        uint32_t sb = st * STG_B;
#pragma unroll
        for (int ks = 0; ks < 2; ks++) {
            unsigned Ah[2][4], Bh[4][2];
#pragma unroll
            for (int i = 0; i < 2; i++) {
                uint32_t a = addrA[i] + sb + ks*32;
                ldsm4(Ah[i][0], Ah[i][1], Ah[i][2], Ah[i][3], a);
            }
#pragma unroll
            for (int j2 = 0; j2 < 2; j2++) {
                uint32_t a = addrB[j2] + sb + ks*32;
                unsigned t0, t1, t2, t3;
                ldsm4(t0, t1, t2, t3, a);
                Bh[j2*2][0] = t0; Bh[j2*2][1] = t1; Bh[j2*2+1][0] = t2; Bh[j2*2+1][1] = t3;
            }
#pragma unroll
            for (int i = 0; i < 2; i++)
#pragma unroll
                for (int j = 0; j < 4; j++)
                    MMA_BF16(acc[i][j], Ah[i], Bh[j]);
        }
        __syncthreads();
    }

    int gid = lane >> 2, tig = lane & 3;
#pragma unroll
    for (int i = 0; i < 2; i++)
#pragma unroll
        for (int j = 0; j < 4; j++) {
            int row = blockM + warp_m*32 + i*16 + gid;
            int col = blockN + warp_n*32 + j*8 + tig*2;
            *(__nv_bfloat162*)&g_hidb[(size_t)row*NH + col] =
                __nv_bfloat162(__float2bfloat16(acc[i][j][0]), __float2bfloat16(acc[i][j][1]));
            *(__nv_bfloat162*)&g_hidb[(size_t)(row+8)*NH + col] =
                __nv_bfloat162(__float2bfloat16(acc[i][j][2]), __float2bfloat16(acc[i][j][3]));
        }
}

__global__ __launch_bounds__(256) void logits_kernel(const int* __restrict__ labels,
                                                     const float* __restrict__ w2,
                                                     const float* __restrict__ b2, int l) {
    extern __shared__ float ls[];
    float* hids = ls;              // [32][260]
    float* w2s  = ls + 32*260;     // [256*16]
    float* lg   = w2s + 256*16;    // [32][16]
    __shared__ int labs[32];

    int tid = threadIdx.x;
    int row0 = blockIdx.x * 32;
    if (tid < 32) labs[tid] = labels[row0 + tid];
#pragma unroll
    for (int q = 0; q < 16; q++) w2s[q*256 + tid] = w2[q*256 + tid];
    __syncthreads();

#pragma unroll
    for (int u = 0; u < 8; u++) {
        int idx = u*256 + tid;
        int r = idx >> 6, c4 = idx & 63;
        const __nv_bfloat162* hp =
            (const __nv_bfloat162*)&g_hidb[(size_t)(row0 + r)*NH + l*HH + c4*4];
        __nv_bfloat162 h01 = hp[0], h23 = hp[1];
        float4 cw = *(const float4*)&g_cw1[labs[r]*HH + c4*4];
        float4 o;
        o.x = fmaxf(__bfloat162float(h01.x) + cw.x, 0.f);
        o.y = fmaxf(__bfloat162float(h01.y) + cw.y, 0.f);
        o.z = fmaxf(__bfloat162float(h23.x) + cw.z, 0.f);
        o.w = fmaxf(__bfloat162float(h23.y) + cw.w, 0.f);
        *(float4*)&hids[r*260 + c4*4] = o;
    }
    __syncthreads();

    int r = tid >> 3, kq = tid & 7;
    float a0 = b2[kq*2+0], a1 = b2[kq*2+1];
#pragma unroll 4
    for (int h = 0; h < HH; h++) {
        float hv = hids[r*260 + h];
        float2 w = *(float2*)&w2s[h*16 + kq*2];
        a0 += hv * w.x; a1 += hv * w.y;
    }
    lg[r*16 + kq*2 + 0] = a0;
    lg[r*16 + kq*2 + 1] = a1;
    __syncthreads();

    if (tid < 32) {
        float best = lg[tid*16], second = -1e30f; int bi = 0;
#pragma unroll
        for (int k = 1; k < 16; k++) {
            float v = lg[tid*16 + k];
            if (v > best) { second = best; best = v; bi = k; }
            else if (v > second) second = v;
        }
        int row = row0 + tid;
        int seg = labs[tid]*KC + bi;
        g_seg[row] = seg;
        atomicAdd(&g_hist[(row >> 9)*CK + seg], 1);   // fused histogram
        if (best - second < GAP_TH) {
            int p = atomicAdd(&g_ambN, 1);
            g_amb[p] = row;
        }
    }
}

// 16-row batched fp32 recheck; fixes up g_hist on reassignment.
__global__ __launch_bounds__(256) void recheck_kernel(const float* __restrict__ X,
                                                      const float* __restrict__ w1,
                                                      const float* __restrict__ b1,
                                                      const float* __restrict__ w2,
                                                      const float* __restrict__ b2) {
    extern __shared__ float rsm[];
    float* xr  = rsm;                 // [RB][XR_PITCH]
    float* hid = rsm + RB*XR_PITCH;   // [RB][260]
    __shared__ float lgs[RB*16];
    __shared__ int rows[RB], labv[RB];
    int tid = threadIdx.x;
    int n = g_ambN;
    for (int grp = blockIdx.x; grp*RB < n; grp += gridDim.x) {
        int cnt = min(RB, n - grp*RB);
        if (tid < RB) {
            int rr = (tid < cnt) ? g_amb[grp*RB + tid] : g_amb[grp*RB];
            rows[tid] = rr;
            labv[tid] = g_seg[rr] >> 4;
        }
        __syncthreads();
        for (int j = tid; j < cnt*DD; j += 256) {
            int r = j >> 9, k = j & 511;
            xr[r*XR_PITCH + k] = X[(size_t)rows[r]*DD + k] + g_claccum[labv[r]*DD + k];
        }
        __syncthreads();
        float acc[RB];
#pragma unroll
        for (int r = 0; r < RB; r++) acc[r] = b1[tid];
#pragma unroll 4
        for (int k = 0; k < DD; k++) {
            float w = w1[k*HH + tid];
#pragma unroll
            for (int r = 0; r < RB; r++) acc[r] += xr[r*XR_PITCH + k] * w;
        }
#pragma unroll
        for (int r = 0; r < RB; r++) hid[r*260 + tid] = fmaxf(acc[r], 0.f);
        __syncthreads();
        {
            int r = tid >> 4, k = tid & 15;
            if (r < cnt) {
                float a = b2[k];
#pragma unroll 8
                for (int h = 0; h < HH; h++) a += hid[r*260 + h] * w2[h*KC + k];
                lgs[r*16 + k] = a;
            }
        }
        __syncthreads();
        if (tid < cnt) {
            float best = lgs[tid*16]; int bi = 0;
#pragma unroll
            for (int k = 1; k < KC; k++)
                if (lgs[tid*16 + k] > best) { best = lgs[tid*16 + k]; bi = k; }
            int news = labv[tid]*KC + bi;
            int olds = g_seg[rows[tid]];
            if (news != olds) {
                g_seg[rows[tid]] = news;
                int c = rows[tid] >> 9;
                atomicSub(&g_hist[c*CK + olds], 1);
                atomicAdd(&g_hist[c*CK + news], 1);
            }
        }
        __syncthreads();
    }
}

__global__ __launch_bounds__(1024) void scan_kernel() {
    __shared__ int sc[CK];
    int t = threadIdx.x;
    int run = 0;
#pragma unroll
    for (int ch = 0; ch < 16; ch++) {
        int v[8];
#pragma unroll
        for (int u = 0; u < 8; u++) v[u] = g_hist[(ch*8 + u)*CK + t];
#pragma unroll
        for (int u = 0; u < 8; u++) {
            int x = v[u];
            g_hist[(ch*8 + u)*CK + t] = run;
            run += x;
        }
    }
    sc[t] = run;
    __syncthreads();
    for (int off = 1; off < CK; off <<= 1) {
        int v = (t >= off) ? sc[t - off] : 0;
        __syncthreads();
        sc[t] += v;
        __syncthreads();
    }
    g_segbase[t] = sc[t] - run;
    g_cntI[t] = run;
    g_cnt[t] = (float)run;
}

__global__ __launch_bounds__(512) void scatter_kernel() {
    __shared__ int sg[512];
    int c = blockIdx.x, tid = threadIdx.x;
    sg[tid] = g_seg[c*512 + tid];
    __syncthreads();
    int s = sg[tid], rank = 0;
#pragma unroll 8
    for (int j = 0; j < 512; j++) rank += (j < tid && sg[j] == s) ? 1 : 0;
    g_order[g_segbase[s] + g_hist[c*CK + s] + rank] = c*512 + tid;
}

__global__ __launch_bounds__(512) void mean_kernel(const float* __restrict__ X) {
    __shared__ int idx[2048];
    int seg = blockIdx.x, tid = threadIdx.x;
    int cnt = g_cntI[seg], base = g_segbase[seg];
    float acc = 0.f;
    for (int off = 0; off < cnt; off += 2048) {
        int m = min(2048, cnt - off);
        for (int i = tid; i < m; i += 512) idx[i] = g_order[base + off + i];
        __syncthreads();
        int j = 0;
        for (; j + 4 <= m; j += 4) {
            acc += X[(size_t)idx[j]*DD + tid] + X[(size_t)idx[j+1]*DD + tid]
                 + X[(size_t)idx[j+2]*DD + tid] + X[(size_t)idx[j+3]*DD + tid];
        }
        for (; j < m; j++) acc += X[(size_t)idx[j]*DD + tid];
        __syncthreads();
    }
    int cls = seg >> 4;
    float clv = g_claccum[cls*DD + tid];
    float mean = (acc + (float)cnt * clv) / fmaxf((float)cnt, 1.f);
    g_means[(size_t)seg*DD + tid] = mean;
}

// fp32 refiner GEMM: 64x64 tile, BK=16, cp.async double-buffered.
#define SG_PA 20
#define SG_PB 68
__global__ __launch_bounds__(256) void sgemm_bias(
    const float* __restrict__ A, const float* __restrict__ B,
    const float* __restrict__ bias, float* __restrict__ Cmat)
{
    __shared__ float As[2][64*SG_PA];
    __shared__ float Bs[2][16*SG_PB];
    int tid = threadIdx.x;
    int colBase = blockIdx.x * 64, rowBase = blockIdx.y * 64;
    int ar = tid >> 2, ac = (tid & 3) << 2;
    int br = tid >> 4, bc = (tid & 15) << 2;
    int tx = tid & 15, ty = tid >> 4;
    float acc[4][4] = {};
    uint32_t asb = smem_u32(As), bsb = smem_u32(Bs);

    auto issue = [&](int kt, int st) {
        cpa16(asb + (uint32_t)(st*64*SG_PA + ar*SG_PA + ac)*4,
              A + (size_t)(rowBase + ar)*DD + kt*16 + ac);
        cpa16(bsb + (uint32_t)(st*16*SG_PB + br*SG_PB + bc)*4,
              B + (size_t)(kt*16 + br)*DD + colBase + bc);
        asm volatile("cp.async.commit_group;");
    };
    issue(0, 0);
    for (int kt = 0; kt < 32; kt++) {
        if (kt + 1 < 32) {
            issue(kt + 1, (kt + 1) & 1);
            asm volatile("cp.async.wait_group 1;");
        } else {
            asm volatile("cp.async.wait_group 0;");
        }
        __syncthreads();
        const float* as = As[kt & 1];
        const float* bs = Bs[kt & 1];
#pragma unroll
        for (int kk = 0; kk < 16; kk++) {
            float a[4], b[4];
#pragma unroll
            for (int i = 0; i < 4; i++) a[i] = as[(ty*4 + i)*SG_PA + kk];
            *(float4*)b = *(const float4*)&bs[kk*SG_PB + tx*4];
#pragma unroll
            for (int i = 0; i < 4; i++)
#pragma unroll
                for (int j = 0; j < 4; j++) acc[i][j] += a[i] * b[j];
        }
        __syncthreads();
    }
    float4 bv = *(const float4*)&bias[colBase + tx*4];
#pragma unroll
    for (int i = 0; i < 4; i++) {
        float4 o = make_float4(acc[i][0] + bv.x, acc[i][1] + bv.y,
                               acc[i][2] + bv.z, acc[i][3] + bv.w);
        *(float4*)&Cmat[(size_t)(rowBase + ty*4 + i)*DD + colBase + tx*4] = o;
    }
}

__global__ __launch_bounds__(512) void ln_relu_kernel(
    const float* __restrict__ gw, const float* __restrict__ bw)
{
    __shared__ float red[16];
    int tid = threadIdx.x, row = blockIdx.x;
    float x = g_h[(size_t)row*DD + tid];
    float s = x;
#pragma unroll
    for (int o = 16; o > 0; o >>= 1) s += __shfl_xor_sync(0xffffffffu, s, o);
    if ((tid & 31) == 0) red[tid >> 5] = s;
    __syncthreads();
    float tot = 0.f;
#pragma unroll
    for (int w = 0; w < 16; w++) tot += red[w];
    float m = tot * (1.f/512.f);
    float d = x - m;
    float q = d * d;
    __syncthreads();
#pragma unroll
    for (int o = 16; o > 0; o >>= 1) q += __shfl_xor_sync(0xffffffffu, q, o);
    if ((tid & 31) == 0) red[tid >> 5] = q;
    __syncthreads();
    float tot2 = 0.f;
#pragma unroll
    for (int w = 0; w < 16; w++) tot2 += red[w];
    float v = tot2 * (1.f/512.f);
    float y = d * rsqrtf(v + 1e-5f) * gw[tid] + bw[tid];
    g_h[(size_t)row*DD + tid] = fmaxf(y, 0.f);
}

// lp + claccum update; computes next-level cw1, zeroes hist, resets ambN.
__global__ __launch_bounds__(512) void lp_kernel(int l,
                                                 const float* __restrict__ w1n,
                                                 const float* __restrict__ b1n) {
    __shared__ float cl[DD];
    __shared__ float part[512];
    int c = blockIdx.x, tid = threadIdx.x;
    float s = 0.f, net = 0.f;
#pragma unroll
    for (int k = 0; k < 16; k++) {
        float cn = g_cnt[c*16 + k];
        if (cn > 0.f) { s += g_ref[(size_t)(c*16 + k)*DD + tid]; net += 1.f; }
    }
    float lp = s / fmaxf(net, 1.f);
    g_lp[(size_t)l*CC*DD + c*DD + tid] = lp;
    float newacc = g_claccum[c*DD + tid] + lp;
    g_claccum[c*DD + tid] = newacc;
    if (c == 0 && tid == 0) g_ambN = 0;
    {
        int gi = c*512 + tid;
#pragma unroll
        for (int u = 0; u < 4; u++) g_hist[gi*4 + u] = 0;
    }
    if (w1n) {
        cl[tid] = newacc;
        __syncthreads();
        int h = tid & 255, half = tid >> 8;
        float acc = 0.f;
        int k0 = half * 256;
#pragma unroll 8
        for (int k = k0; k < k0 + 256; k++) acc += cl[k] * w1n[k*HH + h];
        part[tid] = acc;
        __syncthreads();
        if (tid < 256) g_cw1[c*HH + tid] = part[tid] + part[tid + 256] + b1n[tid];
    }
}

__global__ __launch_bounds__(512) void combiner_kernel(
    const float* __restrict__ w1, const float* __restrict__ b1,
    const float* __restrict__ w2, const float* __restrict__ b2,
    float* __restrict__ out)
{
    __shared__ float comb[LV*DD];
    __shared__ float t1[DD];
    int c = blockIdx.x, tid = threadIdx.x;
    for (int j = tid; j < LV*DD; j += 512) {
        int lev = j >> 9, dd = j & 511;
        comb[j] = g_lp[(size_t)lev*CC*DD + c*DD + dd];
    }
    __syncthreads();
    float a = b1[tid];
    for (int i = 0; i < LV*DD; i += 8) {
#pragma unroll
        for (int u = 0; u < 8; u++) a += comb[i+u] * w1[(size_t)(i+u)*DD + tid];
    }
    t1[tid] = fmaxf(a, 0.f);
    __syncthreads();
    float a2 = b2[tid];
    for (int i = 0; i < DD; i += 8) {
#pragma unroll
        for (int u = 0; u < 8; u++) a2 += t1[i+u] * w2[(size_t)(i+u)*DD + tid];
    }
    out[c*DD + tid] = a2;
}

extern "C" void kernel_launch(void* const* d_in, const int* in_sizes, int n_in,
                              void* d_out, int out_size)
{
    const float* X      = (const float*)d_in[0];
    const int*   labels = (const int*)  d_in[1];
    const float* ch_w1  = (const float*)d_in[2];
    const float* ch_b1  = (const float*)d_in[3];
    const float* ch_w2  = (const float*)d_in[4];
    const float* ch_b2  = (const float*)d_in[5];
    const float* ref_w1 = (const float*)d_in[6];
    const float* ref_b1 = (const float*)d_in[7];
    const float* ln_g   = (const float*)d_in[8];
    const float* ln_b   = (const float*)d_in[9];
    const float* ref_w2 = (const float*)d_in[10];
    const float* ref_b2 = (const float*)d_in[11];
    const float* comb_w1 = (const float*)d_in[12];
    const float* comb_b1 = (const float*)d_in[13];
    const float* comb_w2 = (const float*)d_in[14];
    const float* comb_b2 = (const float*)d_in[15];
    float* out = (float*)d_out;

    const int GEMM_SMEM = 3 * STG_B;        // 46080
    const int LOGITS_SMEM = (32*260 + 256*16 + 32*16) * 4;
    const int RECHECK_SMEM = (RB*XR_PITCH + RB*260) * 4;   // 49664
    static int inited = 0;
    if (!inited) {
        cudaFuncSetAttribute(gemm_hid_kernel, cudaFuncAttributeMaxDynamicSharedMemorySize, GEMM_SMEM);
        cudaFuncSetAttribute(logits_kernel, cudaFuncAttributeMaxDynamicSharedMemorySize, LOGITS_SMEM);
        cudaFuncSetAttribute(recheck_kernel, cudaFuncAttributeMaxDynamicSharedMemorySize, RECHECK_SMEM);
        inited = 1;
    }

    float *means_p, *h_p, *ref_p;
    cudaGetSymbolAddress((void**)&means_p, g_means);
    cudaGetSymbolAddress((void**)&h_p,     g_h);
    cudaGetSymbolAddress((void**)&ref_p,   g_ref);

    init_kernel<<<64, 512>>>(ch_b1);
    conv_x_kernel<<<1024, 256>>>(X);
    conv_w1_kernel<<<(LV*DD*HH + 255)/256, 256>>>(ch_w1);
    gemm_hid_kernel<<<dim3(NH/64, NN/128), 256, GEMM_SMEM>>>();

    for (int l = 0; l < LV; l++) {
        logits_kernel<<<NN/32, 256, LOGITS_SMEM>>>(labels,
            ch_w2 + (size_t)l*HH*KC, ch_b2 + (size_t)l*KC, l);
        recheck_kernel<<<1024, 256, RECHECK_SMEM>>>(X,
            ch_w1 + (size_t)l*DD*HH, ch_b1 + (size_t)l*HH,
            ch_w2 + (size_t)l*HH*KC, ch_b2 + (size_t)l*KC);
        scan_kernel<<<1, 1024>>>();
        scatter_kernel<<<128, 512>>>();
        mean_kernel<<<CK, 512>>>(X);
        sgemm_bias<<<dim3(DD/64, CK/64), 256>>>(
            means_p, ref_w1 + (size_t)l*DD*DD, ref_b1 + (size_t)l*DD, h_p);
        ln_relu_kernel<<<CK, 512>>>(ln_g + (size_t)l*DD, ln_b + (size_t)l*DD);
        sgemm_bias<<<dim3(DD/64, CK/64), 256>>>(
            h_p, ref_w2 + (size_t)l*DD*DD, ref_b2 + (size_t)l*DD, ref_p);
        const float* w1n = (l + 1 < LV) ? ch_w1 + (size_t)(l+1)*DD*HH : nullptr;
        const float* b1n = (l + 1 < LV) ? ch_b1 + (size_t)(l+1)*HH : nullptr;
        lp_kernel<<<CC, 512>>>(l, w1n, b1n);
    }
    combiner_kernel<<<CC, 512>>>(comb_w1, comb_b1, comb_w2, comb_b2, out);
}

// round 16
// speedup vs baseline: 1.0264x; 1.0264x over previous
#include <cuda_runtime.h>
#include <cuda_bf16.h>
#include <cstdint>

#define NN 65536
#define DD 512
#define HH 256
#define KC 16
#define LV 3
#define CC 64
#define CK 1024
#define NH 768
#define GAP_TH 5e-3f

__device__ float g_claccum[CC*DD];
__device__ int   g_seg[NN];
__device__ float g_means[CK*DD];
__device__ float g_cnt[CK];
__device__ int   g_cntI[CK];
__device__ int   g_segbase[CK];
__device__ int   g_hist[128*CK];   // [block][seg]
__device__ int   g_order[NN];
__device__ float g_h[CK*DD];
__device__ float g_ref[CK*DD];
__device__ float g_lp[LV*CC*DD];
__device__ float g_cw1[CC*HH];
__device__ int   g_amb[NN];
__device__ int   g_ambN;
__device__ __nv_bfloat16 g_hidb[(size_t)NN*NH];
__device__ __nv_bfloat16 g_xhi[(size_t)NN*DD];
__device__ __nv_bfloat16 g_w1hi[NH*DD];

__device__ __forceinline__ uint32_t smem_u32(const void* p) {
    uint32_t a;
    asm("{ .reg .u64 t; cvta.to.shared.u64 t, %1; cvt.u32.u64 %0, t; }" : "=r"(a) : "l"(p));
    return a;
}
__device__ __forceinline__ void cpa16(uint32_t dst, const void* src) {
    asm volatile("cp.async.cg.shared.global [%0], [%1], 16;" :: "r"(dst), "l"(src));
}
__device__ __forceinline__ void ldsm4(unsigned &r0, unsigned &r1, unsigned &r2, unsigned &r3, uint32_t a) {
    asm volatile("ldmatrix.sync.aligned.m8n8.x4.shared.b16 {%0,%1,%2,%3}, [%4];"
                 : "=r"(r0), "=r"(r1), "=r"(r2), "=r"(r3) : "r"(a));
}
#define MMA_BF16(d, a, b) \
    asm volatile("mma.sync.aligned.m16n8k16.row.col.f32.bf16.bf16.f32 " \
        "{%0,%1,%2,%3},{%4,%5,%6,%7},{%8,%9},{%0,%1,%2,%3};" \
        : "+f"((d)[0]), "+f"((d)[1]), "+f"((d)[2]), "+f"((d)[3]) \
        : "r"((a)[0]), "r"((a)[1]), "r"((a)[2]), "r"((a)[3]), "r"((b)[0]), "r"((b)[1]))

// init: zero claccum + hist, seed level-0 cw1 = b1, reset amb counter
__global__ void init_kernel(const float* __restrict__ b1_0) {
    int i = blockIdx.x * blockDim.x + threadIdx.x;
    if (i < CC*DD) g_claccum[i] = 0.f;
    if (i < CC*HH) g_cw1[i] = b1_0[i & (HH-1)];
#pragma unroll
    for (int u = 0; u < 4; u++) g_hist[i*4 + u] = 0;
    if (i == 0) g_ambN = 0;
}

__global__ void conv_x_kernel(const float* __restrict__ X) {
    for (size_t i = blockIdx.x * blockDim.x + threadIdx.x; i < (size_t)NN*DD/4;
         i += (size_t)gridDim.x * blockDim.x) {
        float4 v = ((const float4*)X)[i];
        __nv_bfloat162* dh = (__nv_bfloat162*)(g_xhi + 4*i);
        dh[0] = __nv_bfloat162(__float2bfloat16(v.x), __float2bfloat16(v.y));
        dh[1] = __nv_bfloat162(__float2bfloat16(v.z), __float2bfloat16(v.w));
    }
}
__global__ void conv_w1_kernel(const float* __restrict__ w1) {
    int i = blockIdx.x * blockDim.x + threadIdx.x;
    if (i >= LV*DD*HH) return;
    int l = i / (DD*HH);
    int r = i % (DD*HH);
    int k = r / HH, h = r % HH;
    size_t dst = (size_t)(l*HH + h) * DD + k;
    g_w1hi[dst] = __float2bfloat16(w1[i]);
}

// HID[N,768] = X @ W1cat, plain bf16 (argmax protected by fp32 recheck band),
// CTA 128x64, BK=32, 3-stage cp.async pipeline; HID stored bf16.
#define STG_B  15360
#define BHI_O  10240

__global__ __launch_bounds__(256) void gemm_hid_kernel() {
    extern __shared__ __nv_bfloat16 smbuf[];
    uint32_t smb = smem_u32(smbuf);
    int tid = threadIdx.x, lane = tid & 31, wid = tid >> 5;
    int warp_m = wid >> 1, warp_n = wid & 1;
    int blockN = blockIdx.x * 64;
    int blockM = blockIdx.y * 128;

    int a_r0 = tid >> 2, a_c = tid & 3;
    int a_r1 = a_r0 + 64;
    int b_r = tid >> 2;

    int a_row_off = lane & 15, a_k8 = (lane >> 4) * 8;
    int bm = lane >> 3;
    int b_n_off = ((bm >> 1) << 3) + (lane & 7);
    int b_k8 = (bm & 1) << 3;

    uint32_t addrA[2], addrB[2];
#pragma unroll
    for (int i = 0; i < 2; i++)
        addrA[i] = smb + (uint32_t)((warp_m*32 + i*16 + a_row_off)*40 + a_k8)*2;
#pragma unroll
    for (int j2 = 0; j2 < 2; j2++)
        addrB[j2] = smb + BHI_O + (uint32_t)((warp_n*32 + j2*16 + b_n_off)*40 + b_k8)*2;

    float acc[2][4][4];
#pragma unroll
    for (int i = 0; i < 2; i++)
#pragma unroll
        for (int j = 0; j < 4; j++)
#pragma unroll
            for (int q = 0; q < 4; q++) acc[i][j][q] = 0.f;

    auto issue = [&](int kt, int stage) {
        int kb = kt * 32;
        uint32_t sb = smb + stage * STG_B;
        size_t g0 = (size_t)(blockM + a_r0)*DD + kb + a_c*8;
        cpa16(sb + (uint32_t)(a_r0*40 + a_c*8)*2, g_xhi + g0);
        size_t g1 = (size_t)(blockM + a_r1)*DD + kb + a_c*8;
        cpa16(sb + (uint32_t)(a_r1*40 + a_c*8)*2, g_xhi + g1);
        size_t gb = (size_t)(blockN + b_r)*DD + kb + a_c*8;
        cpa16(sb + BHI_O + (uint32_t)(b_r*40 + a_c*8)*2, g_w1hi + gb);
        asm volatile("cp.async.commit_group;");
    };

    issue(0, 0);
    issue(1, 1);

    for (int kt = 0; kt < 16; kt++) {
        if (kt < 15) asm volatile("cp.async.wait_group 1;");
        else         asm volatile("cp.async.wait_group 0;");
        __syncthreads();
        int st = kt % 3;
        if (kt + 2 < 16) issue(kt + 2, (kt + 2) % 3);
        uint32_t sb = st * STG_B;
#pragma unroll
        for (int ks = 0; ks < 2; ks++) {
            unsigned Ah[2][4], Bh[4][2];
#pragma unroll
            for (int i = 0; i < 2; i++) {
                uint32_t a = addrA[i] + sb + ks*32;
                ldsm4(Ah[i][0], Ah[i][1], Ah[i][2], Ah[i][3], a);
            }
#pragma unroll
            for (int j2 = 0; j2 < 2; j2++) {
                uint32_t a = addrB[j2] + sb + ks*32;
                unsigned t0, t1, t2, t3;
                ldsm4(t0, t1, t2, t3, a);
                Bh[j2*2][0] = t0; Bh[j2*2][1] = t1; Bh[j2*2+1][0] = t2; Bh[j2*2+1][1] = t3;
            }
#pragma unroll
            for (int i = 0; i < 2; i++)
#pragma unroll
                for (int j = 0; j < 4; j++)
                    MMA_BF16(acc[i][j], Ah[i], Bh[j]);
        }
        __syncthreads();
    }

    int gid = lane >> 2, tig = lane & 3;
#pragma unroll
    for (int i = 0; i < 2; i++)
#pragma unroll
        for (int j = 0; j < 4; j++) {
            int row = blockM + warp_m*32 + i*16 + gid;
            int col = blockN + warp_n*32 + j*8 + tig*2;
            *(__nv_bfloat162*)&g_hidb[(size_t)row*NH + col] =
                __nv_bfloat162(__float2bfloat16(acc[i][j][0]), __float2bfloat16(acc[i][j][1]));
            *(__nv_bfloat162*)&g_hidb[(size_t)(row+8)*NH + col] =
                __nv_bfloat162(__float2bfloat16(acc[i][j][2]), __float2bfloat16(acc[i][j][3]));
        }
}

__global__ __launch_bounds__(256) void logits_kernel(const int* __restrict__ labels,
                                                     const float* __restrict__ w2,
                                                     const float* __restrict__ b2, int l) {
    extern __shared__ float ls[];
    float* hids = ls;              // [32][260]
    float* w2s  = ls + 32*260;     // [256*16]
    float* lg   = w2s + 256*16;    // [32][16]
    __shared__ int labs[32];

    int tid = threadIdx.x;
    int row0 = blockIdx.x * 32;
    if (tid < 32) labs[tid] = labels[row0 + tid];
#pragma unroll
    for (int q = 0; q < 16; q++) w2s[q*256 + tid] = w2[q*256 + tid];
    __syncthreads();

#pragma unroll
    for (int u = 0; u < 8; u++) {
        int idx = u*256 + tid;
        int r = idx >> 6, c4 = idx & 63;
        const __nv_bfloat162* hp =
            (const __nv_bfloat162*)&g_hidb[(size_t)(row0 + r)*NH + l*HH + c4*4];
        __nv_bfloat162 h01 = hp[0], h23 = hp[1];
        float4 cw = *(const float4*)&g_cw1[labs[r]*HH + c4*4];
        float4 o;
        o.x = fmaxf(__bfloat162float(h01.x) + cw.x, 0.f);
        o.y = fmaxf(__bfloat162float(h01.y) + cw.y, 0.f);
        o.z = fmaxf(__bfloat162float(h23.x) + cw.z, 0.f);
        o.w = fmaxf(__bfloat162float(h23.y) + cw.w, 0.f);
        *(float4*)&hids[r*260 + c4*4] = o;
    }
    __syncthreads();

    int r = tid >> 3, kq = tid & 7;
    float a0 = b2[kq*2+0], a1 = b2[kq*2+1];
#pragma unroll 4
    for (int h = 0; h < HH; h++) {
        float hv = hids[r*260 + h];
        float2 w = *(float2*)&w2s[h*16 + kq*2];
        a0 += hv * w.x; a1 += hv * w.y;
    }
    lg[r*16 + kq*2 + 0] = a0;
    lg[r*16 + kq*2 + 1] = a1;
    __syncthreads();

    if (tid < 32) {
        float best = lg[tid*16], second = -1e30f; int bi = 0;
#pragma unroll
        for (int k = 1; k < 16; k++) {
            float v = lg[tid*16 + k];
            if (v > best) { second = best; best = v; bi = k; }
            else if (v > second) second = v;
        }
        int row = row0 + tid;
        int seg = labs[tid]*KC + bi;
        g_seg[row] = seg;
        atomicAdd(&g_hist[(row >> 9)*CK + seg], 1);   // fused histogram
        if (best - second < GAP_TH) {
            int p = atomicAdd(&g_ambN, 1);
            g_amb[p] = row;
        }
    }
}

// 8-row batched fp32 recheck (R14-proven config); fixes up g_hist on reassignment.
__global__ __launch_bounds__(256) void recheck_kernel(const float* __restrict__ X,
                                                      const float* __restrict__ w1,
                                                      const float* __restrict__ b1,
                                                      const float* __restrict__ w2,
                                                      const float* __restrict__ b2) {
    __shared__ float xr[8*DD];
    __shared__ float hid[8*260];
    __shared__ float lgs[8*16];
    __shared__ int rows[8], labv[8];
    int tid = threadIdx.x;
    int n = g_ambN;
    for (int grp = blockIdx.x; grp*8 < n; grp += gridDim.x) {
        int cnt = min(8, n - grp*8);
        if (tid < 8) {
            int rr = (tid < cnt) ? g_amb[grp*8 + tid] : g_amb[grp*8];
            rows[tid] = rr;
            labv[tid] = g_seg[rr] >> 4;
        }
        __syncthreads();
        for (int j = tid; j < cnt*DD; j += 256) {
            int r = j >> 9, k = j & 511;
            xr[r*DD + k] = X[(size_t)rows[r]*DD + k] + g_claccum[labv[r]*DD + k];
        }
        __syncthreads();
        float acc[8];
#pragma unroll
        for (int r = 0; r < 8; r++) acc[r] = b1[tid];
#pragma unroll 4
        for (int k = 0; k < DD; k++) {
            float w = w1[k*HH + tid];
#pragma unroll
            for (int r = 0; r < 8; r++) acc[r] += xr[r*DD + k] * w;
        }
#pragma unroll
        for (int r = 0; r < 8; r++) hid[r*260 + tid] = fmaxf(acc[r], 0.f);
        __syncthreads();
        if (tid < 128) {
            int r = tid >> 4, k = tid & 15;
            if (r < cnt) {
                float a = b2[k];
#pragma unroll 8
                for (int h = 0; h < HH; h++) a += hid[r*260 + h] * w2[h*KC + k];
                lgs[r*16 + k] = a;
            }
        }
        __syncthreads();
        if (tid < cnt) {
            float best = lgs[tid*16]; int bi = 0;
#pragma unroll
            for (int k = 1; k < KC; k++)
                if (lgs[tid*16 + k] > best) { best = lgs[tid*16 + k]; bi = k; }
            int news = labv[tid]*KC + bi;
            int olds = g_seg[rows[tid]];
            if (news != olds) {
                g_seg[rows[tid]] = news;
                int c = rows[tid] >> 9;
                atomicSub(&g_hist[c*CK + olds], 1);
                atomicAdd(&g_hist[c*CK + news], 1);
            }
        }
        __syncthreads();
    }
}

__global__ __launch_bounds__(1024) void scan_kernel() {
    __shared__ int sc[CK];
    int t = threadIdx.x;
    int run = 0;
#pragma unroll
    for (int ch = 0; ch < 16; ch++) {
        int v[8];
#pragma unroll
        for (int u = 0; u < 8; u++) v[u] = g_hist[(ch*8 + u)*CK + t];
#pragma unroll
        for (int u = 0; u < 8; u++) {
            int x = v[u];
            g_hist[(ch*8 + u)*CK + t] = run;
            run += x;
        }
    }
    sc[t] = run;
    __syncthreads();
    for (int off = 1; off < CK; off <<= 1) {
        int v = (t >= off) ? sc[t - off] : 0;
        __syncthreads();
        sc[t] += v;
        __syncthreads();
    }
    g_segbase[t] = sc[t] - run;
    g_cntI[t] = run;
    g_cnt[t] = (float)run;
}

__global__ __launch_bounds__(512) void scatter_kernel() {
    __shared__ int sg[512];
    int c = blockIdx.x, tid = threadIdx.x;
    sg[tid] = g_seg[c*512 + tid];
    __syncthreads();
    int s = sg[tid], rank = 0;
#pragma unroll 8
    for (int j = 0; j < 512; j++) rank += (j < tid && sg[j] == s) ? 1 : 0;
    g_order[g_segbase[s] + g_hist[c*CK + s] + rank] = c*512 + tid;
}

__global__ __launch_bounds__(512) void mean_kernel(const float* __restrict__ X) {
    __shared__ int idx[2048];
    int seg = blockIdx.x, tid = threadIdx.x;
    int cnt = g_cntI[seg], base = g_segbase[seg];
    float acc = 0.f;
    for (int off = 0; off < cnt; off += 2048) {
        int m = min(2048, cnt - off);
        for (int i = tid; i < m; i += 512) idx[i] = g_order[base + off + i];
        __syncthreads();
        int j = 0;
        for (; j + 4 <= m; j += 4) {
            acc += X[(size_t)idx[j]*DD + tid] + X[(size_t)idx[j+1]*DD + tid]
                 + X[(size_t)idx[j+2]*DD + tid] + X[(size_t)idx[j+3]*DD + tid];
        }
        for (; j < m; j++) acc += X[(size_t)idx[j]*DD + tid];
        __syncthreads();
    }
    int cls = seg >> 4;
    float clv = g_claccum[cls*DD + tid];
    float mean = (acc + (float)cnt * clv) / fmaxf((float)cnt, 1.f);
    g_means[(size_t)seg*DD + tid] = mean;
}

// fp32 refiner GEMM: 64x64 tile, BK=16, cp.async double-buffered.
#define SG_PA 20
#define SG_PB 68
__global__ __launch_bounds__(256) void sgemm_bias(
    const float* __restrict__ A, const float* __restrict__ B,
    const float* __restrict__ bias, float* __restrict__ Cmat)
{
    __shared__ float As[2][64*SG_PA];
    __shared__ float Bs[2][16*SG_PB];
    int tid = threadIdx.x;
    int colBase = blockIdx.x * 64, rowBase = blockIdx.y * 64;
    int ar = tid >> 2, ac = (tid & 3) << 2;
    int br = tid >> 4, bc = (tid & 15) << 2;
    int tx = tid & 15, ty = tid >> 4;
    float acc[4][4] = {};
    uint32_t asb = smem_u32(As), bsb = smem_u32(Bs);

    auto issue = [&](int kt, int st) {
        cpa16(asb + (uint32_t)(st*64*SG_PA + ar*SG_PA + ac)*4,
              A + (size_t)(rowBase + ar)*DD + kt*16 + ac);
        cpa16(bsb + (uint32_t)(st*16*SG_PB + br*SG_PB + bc)*4,
              B + (size_t)(kt*16 + br)*DD + colBase + bc);
        asm volatile("cp.async.commit_group;");
    };
    issue(0, 0);
    for (int kt = 0; kt < 32; kt++) {
        if (kt + 1 < 32) {
            issue(kt + 1, (kt + 1) & 1);
            asm volatile("cp.async.wait_group 1;");
        } else {
            asm volatile("cp.async.wait_group 0;");
        }
        __syncthreads();
        const float* as = As[kt & 1];
        const float* bs = Bs[kt & 1];
#pragma unroll
        for (int kk = 0; kk < 16; kk++) {
            float a[4], b[4];
#pragma unroll
            for (int i = 0; i < 4; i++) a[i] = as[(ty*4 + i)*SG_PA + kk];
            *(float4*)b = *(const float4*)&bs[kk*SG_PB + tx*4];
#pragma unroll
            for (int i = 0; i < 4; i++)
#pragma unroll
                for (int j = 0; j < 4; j++) acc[i][j] += a[i] * b[j];
        }
        __syncthreads();
    }
    float4 bv = *(const float4*)&bias[colBase + tx*4];
#pragma unroll
    for (int i = 0; i < 4; i++) {
        float4 o = make_float4(acc[i][0] + bv.x, acc[i][1] + bv.y,
                               acc[i][2] + bv.z, acc[i][3] + bv.w);
        *(float4*)&Cmat[(size_t)(rowBase + ty*4 + i)*DD + colBase + tx*4] = o;
    }
}

__global__ __launch_bounds__(512) void ln_relu_kernel(
    const float* __restrict__ gw, const float* __restrict__ bw)
{
    __shared__ float red[16];
    int tid = threadIdx.x, row = blockIdx.x;
    float x = g_h[(size_t)row*DD + tid];
    float s = x;
#pragma unroll
    for (int o = 16; o > 0; o >>= 1) s += __shfl_xor_sync(0xffffffffu, s, o);
    if ((tid & 31) == 0) red[tid >> 5] = s;
    __syncthreads();
    float tot = 0.f;
#pragma unroll
    for (int w = 0; w < 16; w++) tot += red[w];
    float m = tot * (1.f/512.f);
    float d = x - m;
    float q = d * d;
    __syncthreads();
#pragma unroll
    for (int o = 16; o > 0; o >>= 1) q += __shfl_xor_sync(0xffffffffu, q, o);
    if ((tid & 31) == 0) red[tid >> 5] = q;
    __syncthreads();
    float tot2 = 0.f;
#pragma unroll
    for (int w = 0; w < 16; w++) tot2 += red[w];
    float v = tot2 * (1.f/512.f);
    float y = d * rsqrtf(v + 1e-5f) * gw[tid] + bw[tid];
    g_h[(size_t)row*DD + tid] = fmaxf(y, 0.f);
}

// lp + claccum update; computes next-level cw1, zeroes hist, resets ambN.
__global__ __launch_bounds__(512) void lp_kernel(int l,
                                                 const float* __restrict__ w1n,
                                                 const float* __restrict__ b1n) {
    __shared__ float cl[DD];
    __shared__ float part[512];
    int c = blockIdx.x, tid = threadIdx.x;
    float s = 0.f, net = 0.f;
#pragma unroll
    for (int k = 0; k < 16; k++) {
        float cn = g_cnt[c*16 + k];
        if (cn > 0.f) { s += g_ref[(size_t)(c*16 + k)*DD + tid]; net += 1.f; }
    }
    float lp = s / fmaxf(net, 1.f);
    g_lp[(size_t)l*CC*DD + c*DD + tid] = lp;
    float newacc = g_claccum[c*DD + tid] + lp;
    g_claccum[c*DD + tid] = newacc;
    if (c == 0 && tid == 0) g_ambN = 0;
    {
        int gi = c*512 + tid;
#pragma unroll
        for (int u = 0; u < 4; u++) g_hist[gi*4 + u] = 0;
    }
    if (w1n) {
        cl[tid] = newacc;
        __syncthreads();
        int h = tid & 255, half = tid >> 8;
        float acc = 0.f;
        int k0 = half * 256;
#pragma unroll 8
        for (int k = k0; k < k0 + 256; k++) acc += cl[k] * w1n[k*HH + h];
        part[tid] = acc;
        __syncthreads();
        if (tid < 256) g_cw1[c*HH + tid] = part[tid] + part[tid + 256] + b1n[tid];
    }
}

__global__ __launch_bounds__(512) void combiner_kernel(
    const float* __restrict__ w1, const float* __restrict__ b1,
    const float* __restrict__ w2, const float* __restrict__ b2,
    float* __restrict__ out)
{
    __shared__ float comb[LV*DD];
    __shared__ float t1[DD];
    int c = blockIdx.x, tid = threadIdx.x;
    for (int j = tid; j < LV*DD; j += 512) {
        int lev = j >> 9, dd = j & 511;
        comb[j] = g_lp[(size_t)lev*CC*DD + c*DD + dd];
    }
    __syncthreads();
    float a = b1[tid];
    for (int i = 0; i < LV*DD; i += 8) {
#pragma unroll
        for (int u = 0; u < 8; u++) a += comb[i+u] * w1[(size_t)(i+u)*DD + tid];
    }
    t1[tid] = fmaxf(a, 0.f);
    __syncthreads();
    float a2 = b2[tid];
    for (int i = 0; i < DD; i += 8) {
#pragma unroll
        for (int u = 0; u < 8; u++) a2 += t1[i+u] * w2[(size_t)(i+u)*DD + tid];
    }
    out[c*DD + tid] = a2;
}

extern "C" void kernel_launch(void* const* d_in, const int* in_sizes, int n_in,
                              void* d_out, int out_size)
{
    const float* X      = (const float*)d_in[0];
    const int*   labels = (const int*)  d_in[1];
    const float* ch_w1  = (const float*)d_in[2];
    const float* ch_b1  = (const float*)d_in[3];
    const float* ch_w2  = (const float*)d_in[4];
    const float* ch_b2  = (const float*)d_in[5];
    const float* ref_w1 = (const float*)d_in[6];
    const float* ref_b1 = (const float*)d_in[7];
    const float* ln_g   = (const float*)d_in[8];
    const float* ln_b   = (const float*)d_in[9];
    const float* ref_w2 = (const float*)d_in[10];
    const float* ref_b2 = (const float*)d_in[11];
    const float* comb_w1 = (const float*)d_in[12];
    const float* comb_b1 = (const float*)d_in[13];
    const float* comb_w2 = (const float*)d_in[14];
    const float* comb_b2 = (const float*)d_in[15];
    float* out = (float*)d_out;

    const int GEMM_SMEM = 3 * STG_B;        // 46080
    const int LOGITS_SMEM = (32*260 + 256*16 + 32*16) * 4;
    static int inited = 0;
    if (!inited) {
        cudaFuncSetAttribute(gemm_hid_kernel, cudaFuncAttributeMaxDynamicSharedMemorySize, GEMM_SMEM);
        cudaFuncSetAttribute(logits_kernel, cudaFuncAttributeMaxDynamicSharedMemorySize, LOGITS_SMEM);
        inited = 1;
    }

    float *means_p, *h_p, *ref_p;
    cudaGetSymbolAddress((void**)&means_p, g_means);
    cudaGetSymbolAddress((void**)&h_p,     g_h);
    cudaGetSymbolAddress((void**)&ref_p,   g_ref);

    init_kernel<<<64, 512>>>(ch_b1);
    conv_x_kernel<<<1024, 256>>>(X);
    conv_w1_kernel<<<(LV*DD*HH + 255)/256, 256>>>(ch_w1);
    gemm_hid_kernel<<<dim3(NH/64, NN/128), 256, GEMM_SMEM>>>();

    for (int l = 0; l < LV; l++) {
        logits_kernel<<<NN/32, 256, LOGITS_SMEM>>>(labels,
            ch_w2 + (size_t)l*HH*KC, ch_b2 + (size_t)l*KC, l);
        recheck_kernel<<<1024, 256>>>(X,
            ch_w1 + (size_t)l*DD*HH, ch_b1 + (size_t)l*HH,
            ch_w2 + (size_t)l*HH*KC, ch_b2 + (size_t)l*KC);
        scan_kernel<<<1, 1024>>>();
        scatter_kernel<<<128, 512>>>();
        mean_kernel<<<CK, 512>>>(X);
        sgemm_bias<<<dim3(DD/64, CK/64), 256>>>(
            means_p, ref_w1 + (size_t)l*DD*DD, ref_b1 + (size_t)l*DD, h_p);
        ln_relu_kernel<<<CK, 512>>>(ln_g + (size_t)l*DD, ln_b + (size_t)l*DD);
        sgemm_bias<<<dim3(DD/64, CK/64), 256>>>(
            h_p, ref_w2 + (size_t)l*DD*DD, ref_b2 + (size_t)l*DD, ref_p);
        const float* w1n = (l + 1 < LV) ? ch_w1 + (size_t)(l+1)*DD*HH : nullptr;
        const float* b1n = (l + 1 < LV) ? ch_b1 + (size_t)(l+1)*HH : nullptr;
        lp_kernel<<<CC, 512>>>(l, w1n, b1n);
    }
    combiner_kernel<<<CC, 512>>>(comb_w1, comb_b1, comb_w2, comb_b2, out);
}